// round 12
// baseline (speedup 1.0000x reference)
#include <cuda_runtime.h>
#include <math.h>

// Problem constants
#define NB   32
#define NT   2048
#define ND   1024
#define NDIM 1024
#define NROWS (NB * NT)          // 65536 flattened (b,t) rows
#define NCT  8                   // column tiles in the score GEMM (NDIM / 128)

// ---------------------------------------------------------------------------
// Scratch (no allocations allowed -> __device__ globals)
// ---------------------------------------------------------------------------
__device__ float g_hproj[NB * NDIM];        // last_state @ Wh
__device__ float g_hx   [NB * NDIM];        // last_state @ Wx
__device__ float g_part [NCT * NROWS];      // partial scores per column tile (2 MB)
__device__ float g_alpha[NB * NT];          // softmax weights
__device__ float g_r    [NB * ND];          // alpha-weighted sum of input rows

// ---------------------------------------------------------------------------
// Kernel 1: hproj[b,e] = sum_d ls[b,d]*Wh[d,e]; hx likewise with Wx.
// grid (4,32), 256 threads. Memory served from L2 after first batch.
// ---------------------------------------------------------------------------
__global__ void proj_kernel(const float* __restrict__ ls,
                            const float* __restrict__ Wh,
                            const float* __restrict__ Wx) {
    __shared__ float lss[ND];
    const int b = blockIdx.y;
    const int e = blockIdx.x * 256 + threadIdx.x;
    for (int d = threadIdx.x; d < ND; d += 256) lss[d] = ls[b * ND + d];
    __syncthreads();
    float a0 = 0.f, a1 = 0.f;
#pragma unroll 8
    for (int d = 0; d < ND; d++) {
        float l = lss[d];
        a0 = fmaf(l, Wh[d * NDIM + e], a0);
        a1 = fmaf(l, Wx[d * NDIM + e], a1);
    }
    g_hproj[b * NDIM + e] = a0;
    g_hx[b * NDIM + e]    = a1;
}

// ---------------------------------------------------------------------------
// Kernel 2: fused score GEMM.
//   For each flattened row r=(b,t): partial_score[ct][r] =
//       sum_{e in colTile ct} relu( x[r,:]·Wy[:,e] + hproj[b,e] ) * w[e]
// 128x128x16 tiles, 256 threads, 8x8 microtile held as 32 packed f32x2
// accumulators driven by fma.rn.f32x2 (FFMA2: 2x the 3-reg FFMA rate).
// B tile stored DUPLICATED in smem ({b,b} pairs) so the FFMA2 broadcast
// operand needs no MOVs; A tile stored transposed so row pairs are natural.
// ---------------------------------------------------------------------------
__global__ __launch_bounds__(256, 2)
void score_gemm(const float* __restrict__ X,
                const float* __restrict__ Wy,
                const float* __restrict__ w) {
    __shared__ __align__(16) float As[16 * 132];   // [k][row], padded
    __shared__ __align__(16) float Bs[16 * 264];   // [k][2*col] duplicated

    const int tid = threadIdx.x;
    const int tx = tid & 15;            // column group (8 cols)
    const int ty = tid >> 4;            // row group (8 rows)
    const int colBase = blockIdx.x * 128;
    const int rowBase = blockIdx.y * 128;
    const int b = rowBase >> 11;        // rowBase / 2048 (T divides tile)

    // global-load assignments
    const int arow = tid >> 2, akv = tid & 3;   // A: (row, k-vec4); +64 for 2nd
    const int bk = tid >> 5,  bcv = tid & 31;   // B: (k, col-vec4); +8 for 2nd

    const float* Abase = X + (size_t)rowBase * ND;

    unsigned long long acc[32];
#pragma unroll
    for (int i = 0; i < 32; i++) acc[i] = 0ull;

    float4 aR0, aR1, bR0, bR1;

#define LDG_TILE(kc)                                                          \
    {                                                                         \
        aR0 = *(const float4*)(Abase + (size_t)arow * ND + (kc) * 16 + akv * 4);        \
        aR1 = *(const float4*)(Abase + (size_t)(arow + 64) * ND + (kc) * 16 + akv * 4); \
        bR0 = *(const float4*)(Wy + (size_t)((kc) * 16 + bk) * NDIM + colBase + bcv * 4);     \
        bR1 = *(const float4*)(Wy + (size_t)((kc) * 16 + bk + 8) * NDIM + colBase + bcv * 4); \
    }

#define STS_TILE()                                                            \
    {                                                                         \
        As[(akv * 4 + 0) * 132 + arow] = aR0.x;                               \
        As[(akv * 4 + 1) * 132 + arow] = aR0.y;                               \
        As[(akv * 4 + 2) * 132 + arow] = aR0.z;                               \
        As[(akv * 4 + 3) * 132 + arow] = aR0.w;                               \
        As[(akv * 4 + 0) * 132 + arow + 64] = aR1.x;                          \
        As[(akv * 4 + 1) * 132 + arow + 64] = aR1.y;                          \
        As[(akv * 4 + 2) * 132 + arow + 64] = aR1.z;                          \
        As[(akv * 4 + 3) * 132 + arow + 64] = aR1.w;                          \
        *(float4*)&Bs[bk * 264 + bcv * 8]     = make_float4(bR0.x, bR0.x, bR0.y, bR0.y); \
        *(float4*)&Bs[bk * 264 + bcv * 8 + 4] = make_float4(bR0.z, bR0.z, bR0.w, bR0.w); \
        *(float4*)&Bs[(bk + 8) * 264 + bcv * 8]     = make_float4(bR1.x, bR1.x, bR1.y, bR1.y); \
        *(float4*)&Bs[(bk + 8) * 264 + bcv * 8 + 4] = make_float4(bR1.z, bR1.z, bR1.w, bR1.w); \
    }

    LDG_TILE(0);
    STS_TILE();
    __syncthreads();

    for (int kc = 0; kc < 64; kc++) {
        if (kc < 63) LDG_TILE(kc + 1);
#pragma unroll
        for (int k = 0; k < 16; k++) {
            const ulonglong2 av0 = *(const ulonglong2*)(As + k * 132 + ty * 8);
            const ulonglong2 av1 = *(const ulonglong2*)(As + k * 132 + ty * 8 + 4);
            const ulonglong2 bv0 = *(const ulonglong2*)(Bs + k * 264 + tx * 16);
            const ulonglong2 bv1 = *(const ulonglong2*)(Bs + k * 264 + tx * 16 + 4);
            const ulonglong2 bv2 = *(const ulonglong2*)(Bs + k * 264 + tx * 16 + 8);
            const ulonglong2 bv3 = *(const ulonglong2*)(Bs + k * 264 + tx * 16 + 12);
            unsigned long long a2[4] = {av0.x, av0.y, av1.x, av1.y};
            unsigned long long bd[8] = {bv0.x, bv0.y, bv1.x, bv1.y,
                                        bv2.x, bv2.y, bv3.x, bv3.y};
#pragma unroll
            for (int i2 = 0; i2 < 4; i2++) {
#pragma unroll
                for (int j = 0; j < 8; j++) {
                    asm("fma.rn.f32x2 %0, %1, %2, %0;"
                        : "+l"(acc[i2 * 8 + j])
                        : "l"(a2[i2]), "l"(bd[j]));
                }
            }
        }
        __syncthreads();
        if (kc < 63) {
            STS_TILE();
            __syncthreads();
        }
    }

    // Epilogue: relu(acc + hproj)*w, reduce over this block's 128 columns.
    const int c0 = colBase + tx * 8;
    float hp[8], wv[8];
#pragma unroll
    for (int j = 0; j < 8; j++) {
        hp[j] = g_hproj[b * NDIM + c0 + j];
        wv[j] = w[c0 + j];
    }
    float s[8];
#pragma unroll
    for (int i = 0; i < 8; i++) s[i] = 0.f;
#pragma unroll
    for (int i2 = 0; i2 < 4; i2++) {
#pragma unroll
        for (int j = 0; j < 8; j++) {
            const unsigned long long u = acc[i2 * 8 + j];
            const float lo = __uint_as_float((unsigned)u);
            const float hi = __uint_as_float((unsigned)(u >> 32));
            s[2 * i2]     += fmaxf(lo + hp[j], 0.f) * wv[j];
            s[2 * i2 + 1] += fmaxf(hi + hp[j], 0.f) * wv[j];
        }
    }
    // cross-thread (tx) reduction via smem (reuse As: 2048 <= 2112 floats)
    float* red = As;
#pragma unroll
    for (int i = 0; i < 8; i++) red[(ty * 8 + i) * 16 + tx] = s[i];
    __syncthreads();
    if (tid < 128) {
        float sum = 0.f;
#pragma unroll
        for (int x2 = 0; x2 < 16; x2++) sum += red[tid * 16 + x2];
        g_part[blockIdx.x * NROWS + rowBase + tid] = sum;
    }
#undef LDG_TILE
#undef STS_TILE
}

// ---------------------------------------------------------------------------
// Kernel 3: per-batch softmax over T (sums the 8 column-tile partials);
// also zero-initializes g_r for the following atomic accumulation.
// ---------------------------------------------------------------------------
__global__ void softmax_kernel() {
    const int b = blockIdx.x;
    const int tid = threadIdx.x;
    __shared__ float sc[NT];
    __shared__ float wred[8];

    for (int d = tid; d < ND; d += 256) g_r[b * ND + d] = 0.f;

    float lmax = -1e30f;
    for (int t = tid; t < NT; t += 256) {
        float sum = 0.f;
#pragma unroll
        for (int p = 0; p < NCT; p++) sum += g_part[p * NROWS + b * NT + t];
        sc[t] = sum;
        lmax = fmaxf(lmax, sum);
    }
    for (int o = 16; o; o >>= 1) lmax = fmaxf(lmax, __shfl_xor_sync(0xffffffffu, lmax, o));
    if ((tid & 31) == 0) wred[tid >> 5] = lmax;
    __syncthreads();
    float mx = wred[0];
#pragma unroll
    for (int i = 1; i < 8; i++) mx = fmaxf(mx, wred[i]);
    __syncthreads();

    float lsum = 0.f;
    for (int t = tid; t < NT; t += 256) {
        float e = expf(sc[t] - mx);
        sc[t] = e;
        lsum += e;
    }
    for (int o = 16; o; o >>= 1) lsum += __shfl_xor_sync(0xffffffffu, lsum, o);
    if ((tid & 31) == 0) wred[tid >> 5] = lsum;
    __syncthreads();
    float tot = 0.f;
#pragma unroll
    for (int i = 0; i < 8; i++) tot += wred[i];
    const float inv = 1.f / tot;
    for (int t = tid; t < NT; t += 256) g_alpha[b * NT + t] = sc[t] * inv;
}

// ---------------------------------------------------------------------------
// Kernel 4: r[b,d] = sum_t alpha[b,t] * x[b,t,d]  (memory-bound, 256 MB read)
// grid (4, 32, 8): t split in 8 chunks -> 1024 blocks; atomicAdd into g_r.
// ---------------------------------------------------------------------------
__global__ void r_kernel(const float* __restrict__ X) {
    const int d = blockIdx.x * 256 + threadIdx.x;
    const int b = blockIdx.y;
    const int tc = blockIdx.z;
    __shared__ float al[256];
    al[threadIdx.x] = g_alpha[b * NT + tc * 256 + threadIdx.x];
    __syncthreads();
    const float* xp = X + ((size_t)b * NT + tc * 256) * ND + d;
    float acc = 0.f;
#pragma unroll 8
    for (int t = 0; t < 256; t++) acc = fmaf(al[t], xp[(size_t)t * ND], acc);
    atomicAdd(&g_r[b * ND + d], acc);
}

// ---------------------------------------------------------------------------
// Kernel 5: out[b,e] = relu( sum_d r[b,d]*Wp[d,e] + hx[b,e] )
// ---------------------------------------------------------------------------
__global__ void out_kernel(const float* __restrict__ Wp, float* __restrict__ out) {
    __shared__ float rs[ND];
    const int b = blockIdx.y;
    const int e = blockIdx.x * 256 + threadIdx.x;
    for (int d = threadIdx.x; d < ND; d += 256) rs[d] = g_r[b * ND + d];
    __syncthreads();
    float a = g_hx[b * NDIM + e];
#pragma unroll 8
    for (int d = 0; d < ND; d++) a = fmaf(rs[d], Wp[d * NDIM + e], a);
    out[b * NDIM + e] = fmaxf(a, 0.f);
}

// ---------------------------------------------------------------------------
// Launch: inputs per metadata order:
// input_states, last_state, Wy, Wh, w, Wp, Wx
// ---------------------------------------------------------------------------
extern "C" void kernel_launch(void* const* d_in, const int* in_sizes, int n_in,
                              void* d_out, int out_size) {
    const float* X  = (const float*)d_in[0];
    const float* ls = (const float*)d_in[1];
    const float* Wy = (const float*)d_in[2];
    const float* Wh = (const float*)d_in[3];
    const float* w  = (const float*)d_in[4];
    const float* Wp = (const float*)d_in[5];
    const float* Wx = (const float*)d_in[6];
    float* out = (float*)d_out;

    proj_kernel<<<dim3(NDIM / 256, NB), 256>>>(ls, Wh, Wx);
    score_gemm<<<dim3(NCT, NROWS / 128), 256>>>(X, Wy, w);
    softmax_kernel<<<NB, 256>>>();
    r_kernel<<<dim3(ND / 256, NB, NT / 256), 256>>>(X);
    out_kernel<<<dim3(NDIM / 256, NB), 256>>>(Wp, out);
}

// round 14
// speedup vs baseline: 5.9278x; 5.9278x over previous
#include <cuda_runtime.h>
#include <cuda_bf16.h>
#include <math.h>
#include <stdint.h>

// Problem constants
#define NB   32
#define NT   2048
#define ND   1024
#define NDIM 1024
#define NROWS (NB * NT)          // 65536 flattened (b,t) rows
#define NCT  8                   // column passes in the score GEMM (NDIM / 128)

// ---------------------------------------------------------------------------
// Scratch (no allocations allowed -> __device__ globals)
// ---------------------------------------------------------------------------
__device__ float g_hproj[NB * NDIM];              // last_state @ Wh
__device__ float g_hx   [NB * NDIM];              // last_state @ Wx
__device__ float g_part [NCT * NROWS];            // partial scores per col pass
__device__ float g_alpha[NB * NT];                // softmax weights
__device__ float g_r    [NB * ND];                // alpha-weighted sum of rows
__device__ __nv_bfloat16 g_WyT_hi[NDIM * ND];     // Wy^T high bf16  [n][k]
__device__ __nv_bfloat16 g_WyT_lo[NDIM * ND];     // Wy^T residual   [n][k]
__device__ __nv_bfloat16 g_Xhi[(size_t)NROWS * ND];  // X high bf16  [row][k]
__device__ __nv_bfloat16 g_Xlo[(size_t)NROWS * ND];  // X residual   [row][k]

// ---------------------------------------------------------------------------
// PTX helpers (base-ISA only: ldmatrix / mma.sync / cp.async — no tcgen05)
// ---------------------------------------------------------------------------
__device__ __forceinline__ uint32_t smem_u32(const void* p) {
    uint32_t a;
    asm("{ .reg .u64 t; cvta.to.shared.u64 t, %1; cvt.u32.u64 %0, t; }"
        : "=r"(a) : "l"(p));
    return a;
}
__device__ __forceinline__ void cpa16(uint32_t dst, const void* src) {
    asm volatile("cp.async.cg.shared.global [%0], [%1], 16;"
                 :: "r"(dst), "l"(src) : "memory");
}
#define CP_COMMIT() asm volatile("cp.async.commit_group;" ::: "memory")
#define CP_WAIT2()  asm volatile("cp.async.wait_group 2;" ::: "memory")

__device__ __forceinline__ void ldsm_x4(uint32_t r[4], uint32_t addr) {
    asm volatile("ldmatrix.sync.aligned.m8n8.x4.shared.b16 {%0,%1,%2,%3}, [%4];"
                 : "=r"(r[0]), "=r"(r[1]), "=r"(r[2]), "=r"(r[3]) : "r"(addr));
}
__device__ __forceinline__ void mma16816(float c[4],
                                         const uint32_t a[4],
                                         uint32_t b0, uint32_t b1) {
    asm volatile(
        "mma.sync.aligned.m16n8k16.row.col.f32.bf16.bf16.f32 "
        "{%0,%1,%2,%3}, {%4,%5,%6,%7}, {%8,%9}, {%0,%1,%2,%3};"
        : "+f"(c[0]), "+f"(c[1]), "+f"(c[2]), "+f"(c[3])
        : "r"(a[0]), "r"(a[1]), "r"(a[2]), "r"(a[3]), "r"(b0), "r"(b1));
}

// ---------------------------------------------------------------------------
// Kernel -1: split X (fp32) into bf16 hi/lo planes
// ---------------------------------------------------------------------------
__global__ void x_split(const float4* __restrict__ X4) {
    const size_t idx = (size_t)blockIdx.x * 256 + threadIdx.x;  // one float4
    const float4 f = X4[idx];
    const __nv_bfloat16 h0 = __float2bfloat16(f.x);
    const __nv_bfloat16 h1 = __float2bfloat16(f.y);
    const __nv_bfloat16 h2 = __float2bfloat16(f.z);
    const __nv_bfloat16 h3 = __float2bfloat16(f.w);
    union { __nv_bfloat162 b; unsigned u; } p01, p23, q01, q23;
    p01.b = __halves2bfloat162(h0, h1);
    p23.b = __halves2bfloat162(h2, h3);
    q01.b = __floats2bfloat162_rn(f.x - __bfloat162float(h0),
                                  f.y - __bfloat162float(h1));
    q23.b = __floats2bfloat162_rn(f.z - __bfloat162float(h2),
                                  f.w - __bfloat162float(h3));
    ((uint2*)g_Xhi)[idx] = make_uint2(p01.u, p23.u);
    ((uint2*)g_Xlo)[idx] = make_uint2(q01.u, q23.u);
}

// ---------------------------------------------------------------------------
// Kernel 0: transpose + split Wy -> g_WyT_hi/lo  (bf16, [n][k])
// ---------------------------------------------------------------------------
__global__ void wy_prep(const float* __restrict__ Wy) {
    __shared__ float t[32][33];
    const int k0 = blockIdx.x * 32, n0 = blockIdx.y * 32;
    for (int i = threadIdx.y; i < 32; i += 8)
        t[i][threadIdx.x] = Wy[(size_t)(k0 + i) * NDIM + n0 + threadIdx.x];
    __syncthreads();
    for (int i = threadIdx.y; i < 32; i += 8) {
        const int n = n0 + i, k = k0 + threadIdx.x;
        const float f = t[threadIdx.x][i];
        const __nv_bfloat16 h = __float2bfloat16(f);
        const float r = f - __bfloat162float(h);
        g_WyT_hi[(size_t)n * ND + k] = h;
        g_WyT_lo[(size_t)n * ND + k] = __float2bfloat16(r);
    }
}

// ---------------------------------------------------------------------------
// Kernel 1: hproj = ls@Wh ; hx = ls@Wx
// ---------------------------------------------------------------------------
__global__ void proj_kernel(const float* __restrict__ ls,
                            const float* __restrict__ Wh,
                            const float* __restrict__ Wx) {
    __shared__ float lss[ND];
    const int b = blockIdx.y;
    const int e = blockIdx.x * 256 + threadIdx.x;
    for (int d = threadIdx.x; d < ND; d += 256) lss[d] = ls[b * ND + d];
    __syncthreads();
    float a0 = 0.f, a1 = 0.f;
#pragma unroll 8
    for (int d = 0; d < ND; d++) {
        float l = lss[d];
        a0 = fmaf(l, Wh[d * NDIM + e], a0);
        a1 = fmaf(l, Wx[d * NDIM + e], a1);
    }
    g_hproj[b * NDIM + e] = a0;
    g_hx[b * NDIM + e]    = a1;
}

// ---------------------------------------------------------------------------
// Kernel 2: fused score GEMM via mma.sync bf16 (3-term split).
// Block tile 128x128, 8 warps (2x4) of 64x32, K in 16 chunks of 64,
// 3-stage cp.async pipeline. Grid (NCT=8 colPasses fastest, 512 rowTiles).
// ---------------------------------------------------------------------------
#define RPAD   72                 // padded k-extent per smem row (bf16)
#define PLANE  (128 * RPAD * 2)   // 18432 B
#define OFF_AH 0
#define OFF_AL (1 * PLANE)
#define OFF_BH (2 * PLANE)
#define OFF_BL (3 * PLANE)
#define STB    (4 * PLANE)        // 73728 B per stage
#define HDR    4096
#define NSTAGE 3
#define SMEM_TOT (HDR + NSTAGE * STB)   // 225280 B

__device__ __forceinline__ void issue_chunk(uint32_t smb, int stage, int kc,
                                            int rowBase, int colBase, int tid) {
    const uint32_t base = smb + HDR + stage * STB;
#pragma unroll
    for (int i = 0; i < 4; i++) {
        const int idx = tid + 256 * i;
        const int r = idx >> 3, c8 = idx & 7;
        const uint32_t doff = (uint32_t)(r * RPAD + c8 * 8) * 2;
        const size_t gA = (size_t)(rowBase + r) * ND + kc * 64 + c8 * 8;
        const size_t gB = (size_t)(colBase + r) * ND + kc * 64 + c8 * 8;
        cpa16(base + OFF_AH + doff, g_Xhi + gA);
        cpa16(base + OFF_AL + doff, g_Xlo + gA);
        cpa16(base + OFF_BH + doff, g_WyT_hi + gB);
        cpa16(base + OFF_BL + doff, g_WyT_lo + gB);
    }
}

__global__ __launch_bounds__(256, 1)
void score_gemm(const float* __restrict__ w) {
    extern __shared__ char sm[];
    const uint32_t smb = smem_u32(sm);
    const int tid  = threadIdx.x;
    const int wid  = tid >> 5;
    const int lane = tid & 31;
    const int warpM = wid & 1;          // 2 row-warps (64 rows each)
    const int warpN = wid >> 1;         // 4 col-warps (32 cols each)
    const int colBase = blockIdx.x * 128;
    const int rowBase = blockIdx.y * 128;
    const int b = rowBase >> 11;

    float* hp_s = (float*)(sm);          // 128 floats
    float* w_s  = (float*)(sm + 512);    // 128 floats
    float* red  = (float*)(sm + 1024);   // 128*4 floats

    if (tid < 128) {
        hp_s[tid] = g_hproj[b * NDIM + colBase + tid];
        w_s[tid]  = w[colBase + tid];
    }

    // ldmatrix per-lane base indices
    const int g  = lane >> 3, l8 = lane & 7;
    const int aRow = ((g & 1) << 3) + l8;       // + mi*16 + warpM*64
    const int aCol = (g >> 1) << 3;
    const int bRow = ((g >> 1) << 3) + l8;      // + pi*16 + warpN*32
    const int bCol = (g & 1) << 3;

    float acc[4][4][4];
#pragma unroll
    for (int i = 0; i < 4; i++)
#pragma unroll
        for (int j = 0; j < 4; j++)
#pragma unroll
            for (int q = 0; q < 4; q++) acc[i][j][q] = 0.f;

    // Prologue: fill 3 stages
    issue_chunk(smb, 0, 0, rowBase, colBase, tid); CP_COMMIT();
    issue_chunk(smb, 1, 1, rowBase, colBase, tid); CP_COMMIT();
    issue_chunk(smb, 2, 2, rowBase, colBase, tid); CP_COMMIT();

    for (int kc = 0; kc < 16; kc++) {
        const int st = kc % NSTAGE;
        CP_WAIT2();
        __syncthreads();

        const uint32_t base = smb + HDR + st * STB;
        const uint32_t aBaseH = base + OFF_AH +
            (uint32_t)((warpM * 64 + aRow) * RPAD + aCol) * 2;
        const uint32_t aBaseL = aBaseH + (OFF_AL - OFF_AH);
        const uint32_t bBaseH = base + OFF_BH +
            (uint32_t)((warpN * 32 + bRow) * RPAD + bCol) * 2;
        const uint32_t bBaseL = bBaseH + (OFF_BL - OFF_BH);

#pragma unroll
        for (int ks = 0; ks < 4; ks++) {
            const uint32_t k0 = ks * 16 * 2;    // byte offset along k
            uint32_t ah[4][4], al[4][4], bh[2][4], bl[2][4];
#pragma unroll
            for (int mi = 0; mi < 4; mi++) {
                ldsm_x4(ah[mi], aBaseH + (uint32_t)(mi * 16 * RPAD) * 2 + k0);
                ldsm_x4(al[mi], aBaseL + (uint32_t)(mi * 16 * RPAD) * 2 + k0);
            }
#pragma unroll
            for (int pi = 0; pi < 2; pi++) {
                ldsm_x4(bh[pi], bBaseH + (uint32_t)(pi * 16 * RPAD) * 2 + k0);
                ldsm_x4(bl[pi], bBaseL + (uint32_t)(pi * 16 * RPAD) * 2 + k0);
            }
#pragma unroll
            for (int mi = 0; mi < 4; mi++) {
#pragma unroll
                for (int pi = 0; pi < 2; pi++) {
                    mma16816(acc[mi][2 * pi],     ah[mi], bh[pi][0], bh[pi][1]);
                    mma16816(acc[mi][2 * pi + 1], ah[mi], bh[pi][2], bh[pi][3]);
                    mma16816(acc[mi][2 * pi],     ah[mi], bl[pi][0], bl[pi][1]);
                    mma16816(acc[mi][2 * pi + 1], ah[mi], bl[pi][2], bl[pi][3]);
                    mma16816(acc[mi][2 * pi],     al[mi], bh[pi][0], bh[pi][1]);
                    mma16816(acc[mi][2 * pi + 1], al[mi], bh[pi][2], bh[pi][3]);
                }
            }
        }
        __syncthreads();
        if (kc + 3 < 16) issue_chunk(smb, st, kc + 3, rowBase, colBase, tid);
        CP_COMMIT();   // empty groups in the tail keep wait_group bookkeeping exact
    }

    // Epilogue: relu(acc + hproj) . w over this block's 128 cols.
    const int qr = lane >> 2;
    const int c2 = (lane & 3) * 2;
    float rowsum[8];
#pragma unroll
    for (int i = 0; i < 8; i++) rowsum[i] = 0.f;
#pragma unroll
    for (int mi = 0; mi < 4; mi++) {
#pragma unroll
        for (int ni = 0; ni < 4; ni++) {
            const int col = warpN * 32 + ni * 8 + c2;
            const float hp0 = hp_s[col],     wv0 = w_s[col];
            const float hp1 = hp_s[col + 1], wv1 = w_s[col + 1];
            rowsum[mi * 2]     += fmaxf(acc[mi][ni][0] + hp0, 0.f) * wv0
                                + fmaxf(acc[mi][ni][1] + hp1, 0.f) * wv1;
            rowsum[mi * 2 + 1] += fmaxf(acc[mi][ni][2] + hp0, 0.f) * wv0
                                + fmaxf(acc[mi][ni][3] + hp1, 0.f) * wv1;
        }
    }
#pragma unroll
    for (int i = 0; i < 8; i++) {
        rowsum[i] += __shfl_xor_sync(0xffffffffu, rowsum[i], 1);
        rowsum[i] += __shfl_xor_sync(0xffffffffu, rowsum[i], 2);
    }
    __syncthreads();   // header red[] reuse is distinct from stage area; sync for store order
    if ((lane & 3) == 0) {
#pragma unroll
        for (int i = 0; i < 8; i++) {
            const int row = warpM * 64 + (i >> 1) * 16 + (i & 1) * 8 + qr;
            red[row * 4 + warpN] = rowsum[i];
        }
    }
    __syncthreads();
    if (tid < 128) {
        const float s = red[tid * 4] + red[tid * 4 + 1]
                      + red[tid * 4 + 2] + red[tid * 4 + 3];
        g_part[blockIdx.x * NROWS + rowBase + tid] = s;
    }
}

// ---------------------------------------------------------------------------
// Kernel 3: per-batch softmax over T (sums the NCT column-pass partials);
// also zero-initializes g_r for the following atomic accumulation.
// ---------------------------------------------------------------------------
__global__ void softmax_kernel() {
    const int b = blockIdx.x;
    const int tid = threadIdx.x;
    __shared__ float sc[NT];
    __shared__ float wred[8];

    for (int d = tid; d < ND; d += 256) g_r[b * ND + d] = 0.f;

    float lmax = -1e30f;
    for (int t = tid; t < NT; t += 256) {
        float sum = 0.f;
#pragma unroll
        for (int p = 0; p < NCT; p++) sum += g_part[p * NROWS + b * NT + t];
        sc[t] = sum;
        lmax = fmaxf(lmax, sum);
    }
    for (int o = 16; o; o >>= 1) lmax = fmaxf(lmax, __shfl_xor_sync(0xffffffffu, lmax, o));
    if ((tid & 31) == 0) wred[tid >> 5] = lmax;
    __syncthreads();
    float mx = wred[0];
#pragma unroll
    for (int i = 1; i < 8; i++) mx = fmaxf(mx, wred[i]);
    __syncthreads();

    float lsum = 0.f;
    for (int t = tid; t < NT; t += 256) {
        float e = expf(sc[t] - mx);
        sc[t] = e;
        lsum += e;
    }
    for (int o = 16; o; o >>= 1) lsum += __shfl_xor_sync(0xffffffffu, lsum, o);
    if ((tid & 31) == 0) wred[tid >> 5] = lsum;
    __syncthreads();
    float tot = 0.f;
#pragma unroll
    for (int i = 0; i < 8; i++) tot += wred[i];
    const float inv = 1.f / tot;
    for (int t = tid; t < NT; t += 256) g_alpha[b * NT + t] = sc[t] * inv;
}

// ---------------------------------------------------------------------------
// Kernel 4: r[b,d] = sum_t alpha[b,t] * x[b,t,d]
// ---------------------------------------------------------------------------
__global__ void r_kernel(const float* __restrict__ X) {
    const int d = blockIdx.x * 256 + threadIdx.x;
    const int b = blockIdx.y;
    const int tc = blockIdx.z;
    __shared__ float al[256];
    al[threadIdx.x] = g_alpha[b * NT + tc * 256 + threadIdx.x];
    __syncthreads();
    const float* xp = X + ((size_t)b * NT + tc * 256) * ND + d;
    float acc = 0.f;
#pragma unroll 8
    for (int t = 0; t < 256; t++) acc = fmaf(al[t], xp[(size_t)t * ND], acc);
    atomicAdd(&g_r[b * ND + d], acc);
}

// ---------------------------------------------------------------------------
// Kernel 5: out[b,e] = relu( sum_d r[b,d]*Wp[d,e] + hx[b,e] )
// ---------------------------------------------------------------------------
__global__ void out_kernel(const float* __restrict__ Wp, float* __restrict__ out) {
    __shared__ float rs[ND];
    const int b = blockIdx.y;
    const int e = blockIdx.x * 256 + threadIdx.x;
    for (int d = threadIdx.x; d < ND; d += 256) rs[d] = g_r[b * ND + d];
    __syncthreads();
    float a = g_hx[b * NDIM + e];
#pragma unroll 8
    for (int d = 0; d < ND; d++) a = fmaf(rs[d], Wp[d * NDIM + e], a);
    out[b * NDIM + e] = fmaxf(a, 0.f);
}

// ---------------------------------------------------------------------------
// Launch: inputs per metadata order:
// input_states, last_state, Wy, Wh, w, Wp, Wx
// ---------------------------------------------------------------------------
extern "C" void kernel_launch(void* const* d_in, const int* in_sizes, int n_in,
                              void* d_out, int out_size) {
    const float* X  = (const float*)d_in[0];
    const float* ls = (const float*)d_in[1];
    const float* Wy = (const float*)d_in[2];
    const float* Wh = (const float*)d_in[3];
    const float* w  = (const float*)d_in[4];
    const float* Wp = (const float*)d_in[5];
    const float* Wx = (const float*)d_in[6];
    float* out = (float*)d_out;

    cudaFuncSetAttribute(score_gemm, cudaFuncAttributeMaxDynamicSharedMemorySize,
                         SMEM_TOT);

    x_split<<<(NROWS * ND / 4) / 256, 256>>>((const float4*)X);
    wy_prep<<<dim3(32, 32), dim3(32, 8)>>>(Wy);
    proj_kernel<<<dim3(NDIM / 256, NB), 256>>>(ls, Wh, Wx);
    score_gemm<<<dim3(NCT, NROWS / 128), 256, SMEM_TOT>>>(w);
    softmax_kernel<<<NB, 256>>>();
    r_kernel<<<dim3(ND / 256, NB, NT / 256), 256>>>(X);
    out_kernel<<<dim3(NDIM / 256, NB), 256>>>(Wp, out);
}

// round 15
// speedup vs baseline: 8.2739x; 1.3958x over previous
#include <cuda_runtime.h>
#include <cuda_fp16.h>
#include <math.h>
#include <stdint.h>

// Problem constants
#define NB   32
#define NT   2048
#define ND   1024
#define NDIM 1024
#define NROWS (NB * NT)          // 65536 flattened (b,t) rows
#define NCT  8                   // column passes in the score GEMM (NDIM / 128)

// ---------------------------------------------------------------------------
// Scratch (no allocations allowed -> __device__ globals)
// ---------------------------------------------------------------------------
__device__ float g_hproj[NB * NDIM];              // last_state @ Wh
__device__ float g_hx   [NB * NDIM];              // last_state @ Wx
__device__ float g_part [NCT * NROWS];            // partial scores per col pass
__device__ float g_alpha[NB * NT];                // softmax weights
__device__ float g_r    [NB * ND];                // alpha-weighted sum of rows
__device__ __half g_WyT_hi[NDIM * ND];            // Wy^T high fp16  [n][k]
__device__ __half g_WyT_lo[NDIM * ND];            // Wy^T residual   [n][k]
__device__ __half g_Xh[(size_t)NROWS * ND];       // X fp16          [row][k]

// ---------------------------------------------------------------------------
// PTX helpers (base-ISA only: ldmatrix / mma.sync / cp.async)
// ---------------------------------------------------------------------------
__device__ __forceinline__ uint32_t smem_u32(const void* p) {
    uint32_t a;
    asm("{ .reg .u64 t; cvta.to.shared.u64 t, %1; cvt.u32.u64 %0, t; }"
        : "=r"(a) : "l"(p));
    return a;
}
__device__ __forceinline__ void cpa16(uint32_t dst, const void* src) {
    asm volatile("cp.async.cg.shared.global [%0], [%1], 16;"
                 :: "r"(dst), "l"(src) : "memory");
}
#define CP_COMMIT() asm volatile("cp.async.commit_group;" ::: "memory")
#define CP_WAIT2()  asm volatile("cp.async.wait_group 2;" ::: "memory")

__device__ __forceinline__ void ldsm_x4(uint32_t r[4], uint32_t addr) {
    asm volatile("ldmatrix.sync.aligned.m8n8.x4.shared.b16 {%0,%1,%2,%3}, [%4];"
                 : "=r"(r[0]), "=r"(r[1]), "=r"(r[2]), "=r"(r[3]) : "r"(addr));
}
__device__ __forceinline__ void mma16816(float c[4],
                                         const uint32_t a[4],
                                         uint32_t b0, uint32_t b1) {
    asm volatile(
        "mma.sync.aligned.m16n8k16.row.col.f32.f16.f16.f32 "
        "{%0,%1,%2,%3}, {%4,%5,%6,%7}, {%8,%9}, {%0,%1,%2,%3};"
        : "+f"(c[0]), "+f"(c[1]), "+f"(c[2]), "+f"(c[3])
        : "r"(a[0]), "r"(a[1]), "r"(a[2]), "r"(a[3]), "r"(b0), "r"(b1));
}

// ---------------------------------------------------------------------------
// Kernel -1: convert X (fp32) to a single fp16 plane
// ---------------------------------------------------------------------------
__global__ void x_conv(const float4* __restrict__ X4) {
    const size_t idx = (size_t)blockIdx.x * 256 + threadIdx.x;  // one float4
    const float4 f = X4[idx];
    union { __half2 h; unsigned u; } p01, p23;
    p01.h = __floats2half2_rn(f.x, f.y);
    p23.h = __floats2half2_rn(f.z, f.w);
    ((uint2*)g_Xh)[idx] = make_uint2(p01.u, p23.u);
}

// ---------------------------------------------------------------------------
// Kernel 0: transpose + split Wy -> g_WyT_hi/lo  (fp16, [n][k])
// ---------------------------------------------------------------------------
__global__ void wy_prep(const float* __restrict__ Wy) {
    __shared__ float t[32][33];
    const int k0 = blockIdx.x * 32, n0 = blockIdx.y * 32;
    for (int i = threadIdx.y; i < 32; i += 8)
        t[i][threadIdx.x] = Wy[(size_t)(k0 + i) * NDIM + n0 + threadIdx.x];
    __syncthreads();
    for (int i = threadIdx.y; i < 32; i += 8) {
        const int n = n0 + i, k = k0 + threadIdx.x;
        const float f = t[threadIdx.x][i];
        const __half h = __float2half_rn(f);
        const float r = f - __half2float(h);
        g_WyT_hi[(size_t)n * ND + k] = h;
        g_WyT_lo[(size_t)n * ND + k] = __float2half_rn(r);
    }
}

// ---------------------------------------------------------------------------
// Kernel 1: hproj = ls@Wh ; hx = ls@Wx
// ---------------------------------------------------------------------------
__global__ void proj_kernel(const float* __restrict__ ls,
                            const float* __restrict__ Wh,
                            const float* __restrict__ Wx) {
    __shared__ float lss[ND];
    const int b = blockIdx.y;
    const int e = blockIdx.x * 256 + threadIdx.x;
    for (int d = threadIdx.x; d < ND; d += 256) lss[d] = ls[b * ND + d];
    __syncthreads();
    float a0 = 0.f, a1 = 0.f;
#pragma unroll 8
    for (int d = 0; d < ND; d++) {
        float l = lss[d];
        a0 = fmaf(l, Wh[d * NDIM + e], a0);
        a1 = fmaf(l, Wx[d * NDIM + e], a1);
    }
    g_hproj[b * NDIM + e] = a0;
    g_hx[b * NDIM + e]    = a1;
}

// ---------------------------------------------------------------------------
// Kernel 2: fused score GEMM via mma.sync fp16 (2-term W split).
// Block tile 256x128, 16 warps (4x4) of 64x32, K in 16 chunks of 64,
// 3-stage cp.async pipeline. Grid (NCT=8 colPasses fastest, 256 rowTiles).
// ---------------------------------------------------------------------------
#define RPAD    72                  // padded k-extent per smem row (halves)
#define APLANE  (256 * RPAD * 2)    // 36864 B
#define BPLANE  (128 * RPAD * 2)    // 18432 B
#define OFF_A   0
#define OFF_BH  APLANE
#define OFF_BL  (APLANE + BPLANE)
#define STB     (APLANE + 2 * BPLANE)   // 73728 B per stage
#define HDR     8192
#define NSTAGE  3
#define SMEM_TOT (HDR + NSTAGE * STB)   // 229376 B

__device__ __forceinline__ void issue_chunk(uint32_t smb, int stage, int kc,
                                            int rowBase, int colBase, int tid) {
    const uint32_t base = smb + HDR + stage * STB;
    // A: 256 rows x 64 k halves = 2048 16B copies
#pragma unroll
    for (int i = 0; i < 4; i++) {
        const int idx = tid + 512 * i;
        const int r = idx >> 3, c8 = idx & 7;
        const uint32_t doff = (uint32_t)(r * RPAD + c8 * 8) * 2;
        cpa16(base + OFF_A + doff,
              g_Xh + (size_t)(rowBase + r) * ND + kc * 64 + c8 * 8);
    }
    // B hi/lo: 128 rows x 64 k halves x 2 planes = 2048 copies
#pragma unroll
    for (int i = 0; i < 2; i++) {
        const int idx = tid + 512 * i;
        const int r = idx >> 3, c8 = idx & 7;
        const uint32_t doff = (uint32_t)(r * RPAD + c8 * 8) * 2;
        const size_t g = (size_t)(colBase + r) * ND + kc * 64 + c8 * 8;
        cpa16(base + OFF_BH + doff, g_WyT_hi + g);
        cpa16(base + OFF_BL + doff, g_WyT_lo + g);
    }
}

__global__ __launch_bounds__(512, 1)
void score_gemm(const float* __restrict__ w) {
    extern __shared__ char sm[];
    const uint32_t smb = smem_u32(sm);
    const int tid  = threadIdx.x;
    const int wid  = tid >> 5;
    const int lane = tid & 31;
    const int warpM = wid & 3;          // 4 row-warps (64 rows each)
    const int warpN = wid >> 2;         // 4 col-warps (32 cols each)
    const int colBase = blockIdx.x * 128;
    const int rowBase = blockIdx.y * 256;
    const int b = rowBase >> 11;

    float* hp_s = (float*)(sm);          // 128 floats
    float* w_s  = (float*)(sm + 512);    // 128 floats
    float* red  = (float*)(sm + 1024);   // 256*4 floats (4KB, within HDR)

    if (tid < 128) {
        hp_s[tid] = g_hproj[b * NDIM + colBase + tid];
        w_s[tid]  = w[colBase + tid];
    }

    // ldmatrix per-lane base indices
    const int g  = lane >> 3, l8 = lane & 7;
    const int aRow = ((g & 1) << 3) + l8;       // + mi*16 + warpM*64
    const int aCol = (g >> 1) << 3;
    const int bRow = ((g >> 1) << 3) + l8;      // + pi*16 + warpN*32
    const int bCol = (g & 1) << 3;

    float acc[4][4][4];
#pragma unroll
    for (int i = 0; i < 4; i++)
#pragma unroll
        for (int j = 0; j < 4; j++)
#pragma unroll
            for (int q = 0; q < 4; q++) acc[i][j][q] = 0.f;

    // Prologue: fill 3 stages
    issue_chunk(smb, 0, 0, rowBase, colBase, tid); CP_COMMIT();
    issue_chunk(smb, 1, 1, rowBase, colBase, tid); CP_COMMIT();
    issue_chunk(smb, 2, 2, rowBase, colBase, tid); CP_COMMIT();

    for (int kc = 0; kc < 16; kc++) {
        const int st = kc % NSTAGE;
        CP_WAIT2();
        __syncthreads();

        const uint32_t base = smb + HDR + st * STB;
        const uint32_t aBase = base + OFF_A +
            (uint32_t)((warpM * 64 + aRow) * RPAD + aCol) * 2;
        const uint32_t bBaseH = base + OFF_BH +
            (uint32_t)((warpN * 32 + bRow) * RPAD + bCol) * 2;
        const uint32_t bBaseL = bBaseH + BPLANE;

#pragma unroll
        for (int ks = 0; ks < 4; ks++) {
            const uint32_t k0 = ks * 16 * 2;    // byte offset along k
            uint32_t ah[4][4], bh[2][4], bl[2][4];
#pragma unroll
            for (int mi = 0; mi < 4; mi++)
                ldsm_x4(ah[mi], aBase + (uint32_t)(mi * 16 * RPAD) * 2 + k0);
#pragma unroll
            for (int pi = 0; pi < 2; pi++) {
                ldsm_x4(bh[pi], bBaseH + (uint32_t)(pi * 16 * RPAD) * 2 + k0);
                ldsm_x4(bl[pi], bBaseL + (uint32_t)(pi * 16 * RPAD) * 2 + k0);
            }
#pragma unroll
            for (int mi = 0; mi < 4; mi++) {
#pragma unroll
                for (int pi = 0; pi < 2; pi++) {
                    mma16816(acc[mi][2 * pi],     ah[mi], bh[pi][0], bh[pi][1]);
                    mma16816(acc[mi][2 * pi + 1], ah[mi], bh[pi][2], bh[pi][3]);
                    mma16816(acc[mi][2 * pi],     ah[mi], bl[pi][0], bl[pi][1]);
                    mma16816(acc[mi][2 * pi + 1], ah[mi], bl[pi][2], bl[pi][3]);
                }
            }
        }
        __syncthreads();
        if (kc + 3 < 16) issue_chunk(smb, st, kc + 3, rowBase, colBase, tid);
        CP_COMMIT();   // empty tail groups keep wait_group bookkeeping exact
    }

    // Epilogue: relu(acc + hproj) . w over this block's 128 cols.
    const int qr = lane >> 2;
    const int c2 = (lane & 3) * 2;
    float rowsum[8];
#pragma unroll
    for (int i = 0; i < 8; i++) rowsum[i] = 0.f;
#pragma unroll
    for (int mi = 0; mi < 4; mi++) {
#pragma unroll
        for (int ni = 0; ni < 4; ni++) {
            const int col = warpN * 32 + ni * 8 + c2;
            const float hp0 = hp_s[col],     wv0 = w_s[col];
            const float hp1 = hp_s[col + 1], wv1 = w_s[col + 1];
            rowsum[mi * 2]     += fmaxf(acc[mi][ni][0] + hp0, 0.f) * wv0
                                + fmaxf(acc[mi][ni][1] + hp1, 0.f) * wv1;
            rowsum[mi * 2 + 1] += fmaxf(acc[mi][ni][2] + hp0, 0.f) * wv0
                                + fmaxf(acc[mi][ni][3] + hp1, 0.f) * wv1;
        }
    }
#pragma unroll
    for (int i = 0; i < 8; i++) {
        rowsum[i] += __shfl_xor_sync(0xffffffffu, rowsum[i], 1);
        rowsum[i] += __shfl_xor_sync(0xffffffffu, rowsum[i], 2);
    }
    __syncthreads();
    if ((lane & 3) == 0) {
#pragma unroll
        for (int i = 0; i < 8; i++) {
            const int row = warpM * 64 + (i >> 1) * 16 + (i & 1) * 8 + qr;
            red[row * 4 + warpN] = rowsum[i];
        }
    }
    __syncthreads();
    if (tid < 256) {
        const float s = red[tid * 4] + red[tid * 4 + 1]
                      + red[tid * 4 + 2] + red[tid * 4 + 3];
        g_part[blockIdx.x * NROWS + rowBase + tid] = s;
    }
}

// ---------------------------------------------------------------------------
// Kernel 3: per-batch softmax over T (sums the NCT column-pass partials);
// also zero-initializes g_r for the following atomic accumulation.
// ---------------------------------------------------------------------------
__global__ void softmax_kernel() {
    const int b = blockIdx.x;
    const int tid = threadIdx.x;
    __shared__ float sc[NT];
    __shared__ float wred[8];

    for (int d = tid; d < ND; d += 256) g_r[b * ND + d] = 0.f;

    float lmax = -1e30f;
    for (int t = tid; t < NT; t += 256) {
        float sum = 0.f;
#pragma unroll
        for (int p = 0; p < NCT; p++) sum += g_part[p * NROWS + b * NT + t];
        sc[t] = sum;
        lmax = fmaxf(lmax, sum);
    }
    for (int o = 16; o; o >>= 1) lmax = fmaxf(lmax, __shfl_xor_sync(0xffffffffu, lmax, o));
    if ((tid & 31) == 0) wred[tid >> 5] = lmax;
    __syncthreads();
    float mx = wred[0];
#pragma unroll
    for (int i = 1; i < 8; i++) mx = fmaxf(mx, wred[i]);
    __syncthreads();

    float lsum = 0.f;
    for (int t = tid; t < NT; t += 256) {
        float e = expf(sc[t] - mx);
        sc[t] = e;
        lsum += e;
    }
    for (int o = 16; o; o >>= 1) lsum += __shfl_xor_sync(0xffffffffu, lsum, o);
    if ((tid & 31) == 0) wred[tid >> 5] = lsum;
    __syncthreads();
    float tot = 0.f;
#pragma unroll
    for (int i = 0; i < 8; i++) tot += wred[i];
    const float inv = 1.f / tot;
    for (int t = tid; t < NT; t += 256) g_alpha[b * NT + t] = sc[t] * inv;
}

// ---------------------------------------------------------------------------
// Kernel 4: r[b,d] = sum_t alpha[b,t] * x[b,t,d]
// ---------------------------------------------------------------------------
__global__ void r_kernel(const float* __restrict__ X) {
    const int d = blockIdx.x * 256 + threadIdx.x;
    const int b = blockIdx.y;
    const int tc = blockIdx.z;
    __shared__ float al[256];
    al[threadIdx.x] = g_alpha[b * NT + tc * 256 + threadIdx.x];
    __syncthreads();
    const float* xp = X + ((size_t)b * NT + tc * 256) * ND + d;
    float acc = 0.f;
#pragma unroll 8
    for (int t = 0; t < 256; t++) acc = fmaf(al[t], xp[(size_t)t * ND], acc);
    atomicAdd(&g_r[b * ND + d], acc);
}

// ---------------------------------------------------------------------------
// Kernel 5: out[b,e] = relu( sum_d r[b,d]*Wp[d,e] + hx[b,e] )
// ---------------------------------------------------------------------------
__global__ void out_kernel(const float* __restrict__ Wp, float* __restrict__ out) {
    __shared__ float rs[ND];
    const int b = blockIdx.y;
    const int e = blockIdx.x * 256 + threadIdx.x;
    for (int d = threadIdx.x; d < ND; d += 256) rs[d] = g_r[b * ND + d];
    __syncthreads();
    float a = g_hx[b * NDIM + e];
#pragma unroll 8
    for (int d = 0; d < ND; d++) a = fmaf(rs[d], Wp[d * NDIM + e], a);
    out[b * NDIM + e] = fmaxf(a, 0.f);
}

// ---------------------------------------------------------------------------
// Launch: inputs per metadata order:
// input_states, last_state, Wy, Wh, w, Wp, Wx
// ---------------------------------------------------------------------------
extern "C" void kernel_launch(void* const* d_in, const int* in_sizes, int n_in,
                              void* d_out, int out_size) {
    const float* X  = (const float*)d_in[0];
    const float* ls = (const float*)d_in[1];
    const float* Wy = (const float*)d_in[2];
    const float* Wh = (const float*)d_in[3];
    const float* w  = (const float*)d_in[4];
    const float* Wp = (const float*)d_in[5];
    const float* Wx = (const float*)d_in[6];
    float* out = (float*)d_out;

    cudaFuncSetAttribute(score_gemm, cudaFuncAttributeMaxDynamicSharedMemorySize,
                         SMEM_TOT);

    x_conv<<<(NROWS * ND / 4) / 256, 256>>>((const float4*)X);
    wy_prep<<<dim3(32, 32), dim3(32, 8)>>>(Wy);
    proj_kernel<<<dim3(NDIM / 256, NB), 256>>>(ls, Wh, Wx);
    score_gemm<<<dim3(NCT, NROWS / 256), 512, SMEM_TOT>>>(w);
    softmax_kernel<<<NB, 256>>>();
    r_kernel<<<dim3(ND / 256, NB, NT / 256), 256>>>(X);
    out_kernel<<<dim3(NDIM / 256, NB), 256>>>(Wp, out);
}